// round 14
// baseline (speedup 1.0000x reference)
#include <cuda_runtime.h>

// Problem constants
#define BB 512      // batch
#define TT 1024     // seq len
#define II 50       // input size
#define HH 32       // hidden
#define GG 128      // 4*H gates
#define BT (BB*TT)
#define PKP 25      // k-pairs (II/2)
#define PROWS 64    // rows per proj tile
#define PNT (BT/PROWS)   // 8192 tiles per direction
#define PGRIDX 296  // persistent proj CTAs per direction (2/SM)
#define XPITCH 26   // padded row pitch in float2

typedef unsigned long long u64;
typedef unsigned int u32;

// ---------------- scratch (device globals: no allocation allowed) ----------------
__device__ float4 g_xp4[2][TT][BB][HH];            // gate quads {zi,zf,zg,zo} (dir=1 time-reversed)
__device__ float  g_yp[2][BT];                     // per-direction partial outputs
// proj weights, k-pair split: [dir][kp][c][qp][h]: gate g=2c+h of cells {qp, qp+16},
//   value = {w[gate_row][2kp], w[gate_row][2kp+1]}
__device__ float2 g_wq2[2][PKP][4][16][2];
__device__ float4 g_bias4[2][HH];                  // {bi,bf,bg,bo} per cell (b_ih+b_hh)
// recurrent weights: [dir][k][j] = {whh[j,k], whh[H+j,k]} / {whh[2H+j,k], whh[3H+j,k]}
__device__ float2 g_whif2[2][HH][HH];
__device__ float2 g_whgo2[2][HH][HH];
__device__ float  g_weff[2*HH];                    // collapsed FC head weight (64)
__device__ float  g_beff;                          // collapsed FC head bias

// ---------------- f32x2 helpers ----------------
__device__ __forceinline__ u64 pk2(float lo, float hi) {
    u64 r; asm("mov.b64 %0, {%1,%2};" : "=l"(r) : "f"(lo), "f"(hi)); return r;
}
__device__ __forceinline__ float2 upk2(u64 v) {
    float2 r; asm("mov.b64 {%0,%1}, %2;" : "=f"(r.x), "=f"(r.y) : "l"(v)); return r;
}
__device__ __forceinline__ void fma2(u64& d, u64 a, u64 b) {
    asm("fma.rn.f32x2 %0, %1, %2, %0;" : "+l"(d) : "l"(a), "l"(b));
}
__device__ __forceinline__ u64 add2(u64 a, u64 b) {
    u64 r; asm("add.rn.f32x2 %0, %1, %2;" : "=l"(r) : "l"(a), "l"(b)); return r;
}

// ---------------- fast transcendentals (MUFU, rel err ~2^-22) ----------------
__device__ __forceinline__ float fex2(float x) { float r; asm("ex2.approx.f32 %0, %1;" : "=f"(r) : "f"(x)); return r; }
__device__ __forceinline__ float frcp(float x) { float r; asm("rcp.approx.f32 %0, %1;" : "=f"(r) : "f"(x)); return r; }
__device__ __forceinline__ float sigm(float x) {
    return frcp(1.0f + fex2(-1.4426950408889634f * x));
}
__device__ __forceinline__ float tanhx(float x) {
    return 1.0f - 2.0f * frcp(1.0f + fex2(2.8853900817779268f * x));
}

// ---------------- cp.async helpers ----------------
__device__ __forceinline__ u32 smem_u32(const void* p) {
    u32 a; asm("{ .reg .u64 t; cvta.to.shared.u64 t, %1; cvt.u32.u64 %0, t; }" : "=r"(a) : "l"(p));
    return a;
}
__device__ __forceinline__ void cpa8(u32 dst, const void* src) {
    asm volatile("cp.async.ca.shared.global [%0], [%1], 8;" :: "r"(dst), "l"(src));
}
#define CPA_COMMIT() asm volatile("cp.async.commit_group;" ::: "memory")
#define CPA_WAIT0()  asm volatile("cp.async.wait_group 0;" ::: "memory")

// ---------------- prep: weight re-layouts + FC-head collapse ----------------
__global__ void prep_kernel(const float* __restrict__ wih_f, const float* __restrict__ whh_f,
                            const float* __restrict__ bih_f, const float* __restrict__ bhh_f,
                            const float* __restrict__ wih_r, const float* __restrict__ whh_r,
                            const float* __restrict__ bih_r, const float* __restrict__ bhh_r,
                            const float* __restrict__ fc1w, const float* __restrict__ fc1b,
                            const float* __restrict__ fc3w, const float* __restrict__ fc3b) {
    int gt = blockIdx.x * blockDim.x + threadIdx.x;
    int nth = gridDim.x * blockDim.x;

    // collapsed FC head: w_eff[j] = sum_k fc3w[k]*fc1w[k,j]
    for (int j = gt; j < 2 * HH; j += nth) {
        float s = 0.f;
        #pragma unroll 8
        for (int k = 0; k < 2 * HH; k++) s = fmaf(fc3w[k], fc1w[k * (2 * HH) + j], s);
        g_weff[j] = s;
    }
    if (gt == 0) {
        float s = fc3b[0];
        for (int k = 0; k < 2 * HH; k++) s = fmaf(fc3w[k], fc1b[k], s);
        g_beff = s;
    }
    // proj weights, k-pair layout (w_ih is (128, 50) row-major; gate rows i,f,g,o = cell, 32+cell, 64+cell, 96+cell)
    for (int n = gt; n < 2 * PKP * 4 * 16 * 2; n += nth) {
        int dir = n / 3200; int rem = n - dir * 3200;
        int kp = rem >> 7; int rem2 = rem & 127;
        int c = rem2 >> 5; int qp = (rem2 >> 1) & 15; int h = rem2 & 1;
        int g = 2 * c + h;
        int cell = qp + ((g >> 2) << 4);       // qp or qp+16
        int gr = ((g & 3) << 5) + cell;        // gate row in (128, II)
        const float* src = dir ? wih_r : wih_f;
        g_wq2[dir][kp][c][qp][h] = make_float2(src[gr * II + 2 * kp],
                                               src[gr * II + 2 * kp + 1]);
    }
    // bias quads
    for (int n = gt; n < 2 * HH; n += nth) {
        int dir = n >> 5; int j = n & 31;
        const float* bi = dir ? bih_r : bih_f;
        const float* bh = dir ? bhh_r : bhh_f;
        g_bias4[dir][j] = make_float4(bi[j] + bh[j],           bi[32 + j] + bh[32 + j],
                                      bi[64 + j] + bh[64 + j], bi[96 + j] + bh[96 + j]);
    }
    // recurrent weight pairs (w_hh is (128, 32) row-major)
    for (int n = gt; n < 2 * HH * HH; n += nth) {
        int dir = n >> 10; int k = (n >> 5) & 31; int j = n & 31;
        const float* src = dir ? whh_r : whh_f;
        g_whif2[dir][k][j] = make_float2(src[j * HH + k],        src[(32 + j) * HH + k]);
        g_whgo2[dir][k][j] = make_float2(src[(64 + j) * HH + k], src[(96 + j) * HH + k]);
    }
}

// ---------------- input projection v7: v6 + zero-ALU staging ----------------
// Staging: src address is LINEAR in n (x + m0*II + 2n); dst (r,kp) tracked incrementally
// (+266 float2 per 256-step, +1 on kp wrap) from a per-thread constant base. No div/mod per tile.
#define PSM_W   (PKP * 4 * 16 * 16)             // 25600 B weights
#define PSM_X   (PROWS * XPITCH * 8)            // 13312 B per x buffer
#define PSM_TOTAL (PSM_W + 2 * PSM_X)           // 52224 B
#define NSTAGE  (PROWS * PKP)                   // 1600 float2 per tile

__global__ void __launch_bounds__(256, 2) proj_kernel(const float* __restrict__ x) {
    extern __shared__ char psm[];
    ulonglong2 (*wqs)[4][16] = (ulonglong2(*)[4][16])psm;     // [PKP][4][16]
    const u32 sb  = smem_u32(psm);
    const u32 xsb = sb + PSM_W;

    const int dir = blockIdx.y;
    const int tid = threadIdx.x;
    const int qp  = tid & 15;
    const int rg  = tid >> 4;

    // per-thread staging constants (computed once)
    const int kp0 = tid % PKP;
    const u32 dof0 = (u32)((tid / PKP) * XPITCH + kp0) * 8;   // dst offset of n = tid

    // stage weights ONCE (verbatim copy; same linear layout as g_wq2[dir])
    for (int n = tid; n < PKP * 4 * 16; n += 256)
        ((uint4*)psm)[n] = ((const uint4*)g_wq2[dir])[n];

    // stage first x tile (zero-ALU incremental addressing)
    int tile = blockIdx.x;
    {
        const float* sp = x + (size_t)tile * (PROWS * II) + 2 * tid;
        u32 d = xsb + dof0;
        int kp = kp0;
        #pragma unroll
        for (int i = 0; i < 7; i++) {
            int n = tid + i * 256;
            if (n < NSTAGE) cpa8(d, sp);
            sp += 512;
            d += 266 * 8; kp += 6;
            if (kp >= PKP) { kp -= PKP; d += 8; }
        }
        CPA_COMMIT(); CPA_WAIT0();
    }
    __syncthreads();

    const float4 b0 = g_bias4[dir][qp];
    const float4 b1 = g_bias4[dir][qp + 16];

    int buf = 0;
    for (; tile < PNT; tile += PGRIDX) {
        const int nxt = tile + PGRIDX;

        // async-stage next tile into the other buffer (flies under compute)
        if (nxt < PNT) {
            const float* sp = x + (size_t)nxt * (PROWS * II) + 2 * tid;
            u32 d = xsb + (u32)(buf ^ 1) * PSM_X + dof0;
            int kp = kp0;
            #pragma unroll
            for (int i = 0; i < 7; i++) {
                int n = tid + i * 256;
                if (n < NSTAGE) cpa8(d, sp);
                sp += 512;
                d += 266 * 8; kp += 6;
                if (kp >= PKP) { kp -= PKP; d += 8; }
            }
            CPA_COMMIT();
        }

        // ---- compute current tile ----
        u64 acc[4][8];
        #pragma unroll
        for (int r = 0; r < 4; r++)
            #pragma unroll
            for (int g = 0; g < 8; g++) acc[r][g] = 0ULL;

        const float2* xrow = (const float2*)(psm + PSM_W + buf * PSM_X) + rg * 4 * XPITCH;

        #pragma unroll 5
        for (int kp = 0; kp < PKP; kp++) {
            ulonglong2 w01 = wqs[kp][0][qp];     // gates {i,f} cell qp   (k-pairs)
            ulonglong2 w23 = wqs[kp][1][qp];     // gates {g,o} cell qp
            ulonglong2 w45 = wqs[kp][2][qp];     // gates {i,f} cell qp+16
            ulonglong2 w67 = wqs[kp][3][qp];     // gates {g,o} cell qp+16
            #pragma unroll
            for (int r = 0; r < 4; r++) {
                u64 xv = *(const u64*)&xrow[r * XPITCH + kp];  // {x[2kp], x[2kp+1]} broadcast LDS.64
                fma2(acc[r][0], w01.x, xv); fma2(acc[r][1], w01.y, xv);
                fma2(acc[r][2], w23.x, xv); fma2(acc[r][3], w23.y, xv);
                fma2(acc[r][4], w45.x, xv); fma2(acc[r][5], w45.y, xv);
                fma2(acc[r][6], w67.x, xv); fma2(acc[r][7], w67.y, xv);
            }
        }

        // ---- epilogue: reduce k-split pairs, add bias, quad STG ----
        const int m0 = tile * PROWS;
        #pragma unroll
        for (int r = 0; r < 4; r++) {
            int m = m0 + rg * 4 + r;
            int b = m >> 10;
            int t = m & (TT - 1);
            int tt = dir ? (TT - 1 - t) : t;
            float2 v0 = upk2(acc[r][0]), v1 = upk2(acc[r][1]);
            float2 v2 = upk2(acc[r][2]), v3 = upk2(acc[r][3]);
            float2 v4 = upk2(acc[r][4]), v5 = upk2(acc[r][5]);
            float2 v6 = upk2(acc[r][6]), v7 = upk2(acc[r][7]);
            float4 o0 = make_float4(v0.x + v0.y + b0.x, v1.x + v1.y + b0.y,
                                    v2.x + v2.y + b0.z, v3.x + v3.y + b0.w);
            float4 o1 = make_float4(v4.x + v4.y + b1.x, v5.x + v5.y + b1.y,
                                    v6.x + v6.y + b1.z, v7.x + v7.y + b1.w);
            g_xp4[dir][tt][b][qp]      = o0;
            g_xp4[dir][tt][b][qp + 16] = o1;
        }

        CPA_WAIT0();
        __syncthreads();
        buf ^= 1;
    }
}

// ---------------- ncu slot-shift dummies (land the capture slot on proj_kernel) ----------------
__global__ void dummy_kernel() {}
__global__ void dummy_kernel2() {}

// ---------------- recurrent scan: warp-per-(dir,batch), barrier-free ----------------
// Round-8 core + split-chain depth 8 (4->8 accumulator chains, 2-level add2 tree).
__global__ void __launch_bounds__(128, 2) lstm_kernel() {
    const int tid = threadIdx.x;
    const int wrp = tid >> 5;
    const int j   = tid & 31;
    const int gw  = blockIdx.x * 4 + wrp;        // 0..1023
    const int dir = gw >> 9;
    const int b   = gw & 511;

    __shared__ __align__(16) float2 hbuf[4][2][HH];     // duplicated h pairs, double-buffered
    __shared__ float ystage[4][32][33];                 // staged y contributions (padded)

    u64 wif[HH], wgo[HH];
    #pragma unroll
    for (int k = 0; k < HH; k++) {
        wif[k] = *(const u64*)&g_whif2[dir][k][j];
        wgo[k] = *(const u64*)&g_whgo2[dir][k][j];
    }
    const float wej = g_weff[dir * HH + j];

    hbuf[wrp][0][j] = make_float2(0.f, 0.f);
    __syncwarp();

    const float4* __restrict__ xp = &g_xp4[dir][0][b][j];
    const int XS = BB * HH;

    // prefetch ring, depth 8
    float4 xr[8];
    #pragma unroll
    for (int p = 0; p < 8; p++) xr[p] = xp[p * XS];

    float c = 0.f;
    int pb = 0;

    #pragma unroll 8
    for (int t = 0; t < TT; t++) {
        float4 xc = xr[t & 7];
        u64 aif[4], ago[4];
        aif[0] = pk2(xc.x, xc.y); ago[0] = pk2(xc.z, xc.w);
        aif[1] = 0ULL; ago[1] = 0ULL;
        aif[2] = 0ULL; ago[2] = 0ULL;
        aif[3] = 0ULL; ago[3] = 0ULL;

        const float2* hb = hbuf[wrp][pb];
        #pragma unroll
        for (int k2 = 0; k2 < HH / 2; k2 += 2) {
            ulonglong2 hqA = *(const ulonglong2*)&hb[2 * k2];       // uniform broadcast LDS.128
            ulonglong2 hqB = *(const ulonglong2*)&hb[2 * k2 + 2];
            fma2(aif[0], wif[2 * k2],     hqA.x);
            fma2(aif[1], wif[2 * k2 + 1], hqA.y);
            fma2(ago[0], wgo[2 * k2],     hqA.x);
            fma2(ago[1], wgo[2 * k2 + 1], hqA.y);
            fma2(aif[2], wif[2 * k2 + 2], hqB.x);
            fma2(aif[3], wif[2 * k2 + 3], hqB.y);
            fma2(ago[2], wgo[2 * k2 + 2], hqB.x);
            fma2(ago[3], wgo[2 * k2 + 3], hqB.y);
        }

        // prefetch t+8 (slot reuse)
        int tn = (t + 8 < TT) ? (t + 8) : (TT - 1);
        xr[t & 7] = xp[tn * XS];

        float2 zif = upk2(add2(add2(aif[0], aif[2]), add2(aif[1], aif[3])));
        float2 zgo = upk2(add2(add2(ago[0], ago[2]), add2(ago[1], ago[3])));
        float ig = sigm(zif.x), fg = sigm(zif.y);
        float gg = tanhx(zgo.x), og = sigm(zgo.y);
        c = fmaf(fg, c, ig * gg);
        float h = og * tanhx(c);

        hbuf[wrp][pb ^ 1][j] = make_float2(h, h);
        ystage[wrp][t & 31][j] = h * wej;        // staged FC contribution (no shfl chain)
        __syncwarp();

        if ((t & 31) == 31) {                    // transpose-reduce 32 outputs, off critical path
            float s = 0.f;
            #pragma unroll
            for (int k = 0; k < 32; k++) s += ystage[wrp][j][k];
            int tg = (t - 31) + j;
            int tout = dir ? (TT - 1 - tg) : tg;
            g_yp[dir][b * TT + tout] = s;
        }
        pb ^= 1;
    }
}

// ---------------- combine: out = yf + yr + b_eff ----------------
__global__ void combine_kernel(float* __restrict__ out) {
    int i = blockIdx.x * blockDim.x + threadIdx.x;
    if (i < BT) out[i] = g_yp[0][i] + g_yp[1][i] + g_beff;
}

extern "C" void kernel_launch(void* const* d_in, const int* in_sizes, int n_in,
                              void* d_out, int out_size) {
    const float* x     = (const float*)d_in[0];
    const float* wih_f = (const float*)d_in[1];
    const float* whh_f = (const float*)d_in[2];
    const float* bih_f = (const float*)d_in[3];
    const float* bhh_f = (const float*)d_in[4];
    const float* wih_r = (const float*)d_in[5];
    const float* whh_r = (const float*)d_in[6];
    const float* bih_r = (const float*)d_in[7];
    const float* bhh_r = (const float*)d_in[8];
    const float* fc1w  = (const float*)d_in[9];
    const float* fc1b  = (const float*)d_in[10];
    const float* fc3w  = (const float*)d_in[11];
    const float* fc3b  = (const float*)d_in[12];
    float* out = (float*)d_out;

    cudaFuncSetAttribute(proj_kernel, cudaFuncAttributeMaxDynamicSharedMemorySize, PSM_TOTAL);

    prep_kernel<<<32, 256>>>(wih_f, whh_f, bih_f, bhh_f,
                             wih_r, whh_r, bih_r, bhh_r,
                             fc1w, fc1b, fc3w, fc3b);

    dummy_kernel<<<1, 32>>>();   // slot shift: capture lands on our 4th launch
    dummy_kernel2<<<1, 32>>>();  // -> proj_kernel

    dim3 pg(PGRIDX, 2);
    proj_kernel<<<pg, 256, PSM_TOTAL>>>(x);

    lstm_kernel<<<256, 128>>>();

    combine_kernel<<<(BT + 255) / 256, 256>>>(out);
}

// round 15
// speedup vs baseline: 1.0239x; 1.0239x over previous
#include <cuda_runtime.h>

// Problem constants
#define BB 512      // batch
#define TT 1024     // seq len
#define II 50       // input size
#define HH 32       // hidden
#define GG 128      // 4*H gates
#define BT (BB*TT)
#define PKP 25      // real k-pairs (II/2)
#define PKPW 26     // weight k-pairs incl zero pad column
#define PROWS 64    // rows per proj tile
#define PNT (BT/PROWS)   // 8192 tiles per direction
#define PGRIDX 296  // persistent proj CTAs per direction (2/SM)
#define XPITCH 26   // padded row pitch in float2 (col 25 = zero pad)

typedef unsigned long long u64;
typedef unsigned int u32;

// ---------------- scratch (device globals: no allocation allowed) ----------------
__device__ float4 g_xp4[2][TT][BB][HH];            // gate quads {zi,zf,zg,zo} (dir=1 time-reversed)
__device__ float  g_yp[2][BT];                     // per-direction partial outputs
// proj weights, k-pair split (kp=25 zeroed): [dir][kp][c][qp][h]
__device__ float2 g_wq2[2][PKPW][4][16][2];
__device__ float4 g_bias4[2][HH];                  // {bi,bf,bg,bo} per cell (b_ih+b_hh)
// recurrent weights: [dir][k][j] = {whh[j,k], whh[H+j,k]} / {whh[2H+j,k], whh[3H+j,k]}
__device__ float2 g_whif2[2][HH][HH];
__device__ float2 g_whgo2[2][HH][HH];
__device__ float  g_weff[2*HH];                    // collapsed FC head weight (64)
__device__ float  g_beff;                          // collapsed FC head bias

// ---------------- f32x2 helpers ----------------
__device__ __forceinline__ u64 pk2(float lo, float hi) {
    u64 r; asm("mov.b64 %0, {%1,%2};" : "=l"(r) : "f"(lo), "f"(hi)); return r;
}
__device__ __forceinline__ float2 upk2(u64 v) {
    float2 r; asm("mov.b64 {%0,%1}, %2;" : "=f"(r.x), "=f"(r.y) : "l"(v)); return r;
}
__device__ __forceinline__ void fma2(u64& d, u64 a, u64 b) {
    asm("fma.rn.f32x2 %0, %1, %2, %0;" : "+l"(d) : "l"(a), "l"(b));
}
__device__ __forceinline__ u64 add2(u64 a, u64 b) {
    u64 r; asm("add.rn.f32x2 %0, %1, %2;" : "=l"(r) : "l"(a), "l"(b)); return r;
}

// ---------------- fast transcendentals (MUFU, rel err ~2^-22) ----------------
__device__ __forceinline__ float fex2(float x) { float r; asm("ex2.approx.f32 %0, %1;" : "=f"(r) : "f"(x)); return r; }
__device__ __forceinline__ float frcp(float x) { float r; asm("rcp.approx.f32 %0, %1;" : "=f"(r) : "f"(x)); return r; }
__device__ __forceinline__ float sigm(float x) {
    return frcp(1.0f + fex2(-1.4426950408889634f * x));
}
__device__ __forceinline__ float tanhx(float x) {
    return 1.0f - 2.0f * frcp(1.0f + fex2(2.8853900817779268f * x));
}

// ---------------- cp.async helpers ----------------
__device__ __forceinline__ u32 smem_u32(const void* p) {
    u32 a; asm("{ .reg .u64 t; cvta.to.shared.u64 t, %1; cvt.u32.u64 %0, t; }" : "=r"(a) : "l"(p));
    return a;
}
__device__ __forceinline__ void cpa8(u32 dst, const void* src) {
    asm volatile("cp.async.ca.shared.global [%0], [%1], 8;" :: "r"(dst), "l"(src));
}
#define CPA_COMMIT() asm volatile("cp.async.commit_group;" ::: "memory")
#define CPA_WAIT0()  asm volatile("cp.async.wait_group 0;" ::: "memory")

// ---------------- prep: weight re-layouts + FC-head collapse ----------------
__global__ void prep_kernel(const float* __restrict__ wih_f, const float* __restrict__ whh_f,
                            const float* __restrict__ bih_f, const float* __restrict__ bhh_f,
                            const float* __restrict__ wih_r, const float* __restrict__ whh_r,
                            const float* __restrict__ bih_r, const float* __restrict__ bhh_r,
                            const float* __restrict__ fc1w, const float* __restrict__ fc1b,
                            const float* __restrict__ fc3w, const float* __restrict__ fc3b) {
    int gt = blockIdx.x * blockDim.x + threadIdx.x;
    int nth = gridDim.x * blockDim.x;

    // collapsed FC head: w_eff[j] = sum_k fc3w[k]*fc1w[k,j]
    for (int j = gt; j < 2 * HH; j += nth) {
        float s = 0.f;
        #pragma unroll 8
        for (int k = 0; k < 2 * HH; k++) s = fmaf(fc3w[k], fc1w[k * (2 * HH) + j], s);
        g_weff[j] = s;
    }
    if (gt == 0) {
        float s = fc3b[0];
        for (int k = 0; k < 2 * HH; k++) s = fmaf(fc3w[k], fc1b[k], s);
        g_beff = s;
    }
    // proj weights, k-pair layout incl zero pad kp=25
    // (w_ih is (128, 50) row-major; gate rows i,f,g,o = cell, 32+cell, 64+cell, 96+cell)
    for (int n = gt; n < 2 * PKPW * 4 * 16 * 2; n += nth) {
        int dir = n / (PKPW * 128); int rem = n - dir * (PKPW * 128);
        int kp = rem >> 7; int rem2 = rem & 127;
        int c = rem2 >> 5; int qp = (rem2 >> 1) & 15; int h = rem2 & 1;
        int g = 2 * c + h;
        int cell = qp + ((g >> 2) << 4);       // qp or qp+16
        int gr = ((g & 3) << 5) + cell;        // gate row in (128, II)
        const float* src = dir ? wih_r : wih_f;
        float2 v = make_float2(0.f, 0.f);
        if (kp < PKP) v = make_float2(src[gr * II + 2 * kp], src[gr * II + 2 * kp + 1]);
        g_wq2[dir][kp][c][qp][h] = v;
    }
    // bias quads
    for (int n = gt; n < 2 * HH; n += nth) {
        int dir = n >> 5; int j = n & 31;
        const float* bi = dir ? bih_r : bih_f;
        const float* bh = dir ? bhh_r : bhh_f;
        g_bias4[dir][j] = make_float4(bi[j] + bh[j],           bi[32 + j] + bh[32 + j],
                                      bi[64 + j] + bh[64 + j], bi[96 + j] + bh[96 + j]);
    }
    // recurrent weight pairs (w_hh is (128, 32) row-major)
    for (int n = gt; n < 2 * HH * HH; n += nth) {
        int dir = n >> 10; int k = (n >> 5) & 31; int j = n & 31;
        const float* src = dir ? whh_r : whh_f;
        g_whif2[dir][k][j] = make_float2(src[j * HH + k],        src[(32 + j) * HH + k]);
        g_whgo2[dir][k][j] = make_float2(src[(64 + j) * HH + k], src[(96 + j) * HH + k]);
    }
}

// ---------------- input projection v8: k-quad x loads (10 wf / 32 FFMA2) ----------------
// Thread (qp = tid&15, rg = tid>>4): rows {4rg..4rg+3}, gates = cells {qp, qp+16} x {i,f,g,o}.
// acc[r][g] u64 = {even-k partial, odd-k partial} of gate g, row r.
// Per kp-pair: 8 LDS.128 (w, 16-distinct) + 4 broadcast LDS.128 (x k-quads) + 64 FFMA2.
#define PSM_W   (PKPW * 4 * 16 * 16)            // 26624 B weights
#define PSM_X   (PROWS * XPITCH * 8)            // 13312 B per x buffer
#define PSM_TOTAL (PSM_W + 2 * PSM_X)           // 53248 B
#define NSTAGE  (PROWS * PKP)                   // 1600 float2 per tile

__global__ void __launch_bounds__(256, 2) proj_kernel(const float* __restrict__ x) {
    extern __shared__ char psm[];
    ulonglong2 (*wqs)[4][16] = (ulonglong2(*)[4][16])psm;     // [PKPW][4][16]
    const u32 sb  = smem_u32(psm);
    const u32 xsb = sb + PSM_W;

    const int dir = blockIdx.y;
    const int tid = threadIdx.x;
    const int qp  = tid & 15;
    const int rg  = tid >> 4;

    // per-thread staging constants (computed once)
    const int kp0 = tid % PKP;
    const u32 dof0 = (u32)((tid / PKP) * XPITCH + kp0) * 8;   // dst offset of n = tid

    // stage weights ONCE (verbatim copy; same linear layout as g_wq2[dir])
    for (int n = tid; n < PKPW * 4 * 16; n += 256)
        ((uint4*)psm)[n] = ((const uint4*)g_wq2[dir])[n];

    // zero the x pad column (kp=25) in BOTH buffers (0 * garbage would NaN otherwise)
    if (tid < 2 * PROWS) {
        int bf = tid >> 6, r = tid & 63;
        *(float2*)(psm + PSM_W + bf * PSM_X + (r * XPITCH + PKP) * 8) = make_float2(0.f, 0.f);
    }

    // stage first x tile (zero-ALU incremental addressing)
    int tile = blockIdx.x;
    {
        const float* sp = x + (size_t)tile * (PROWS * II) + 2 * tid;
        u32 d = xsb + dof0;
        int kp = kp0;
        #pragma unroll
        for (int i = 0; i < 7; i++) {
            int n = tid + i * 256;
            if (n < NSTAGE) cpa8(d, sp);
            sp += 512;
            d += 266 * 8; kp += 6;
            if (kp >= PKP) { kp -= PKP; d += 8; }
        }
        CPA_COMMIT(); CPA_WAIT0();
    }
    __syncthreads();

    const float4 b0 = g_bias4[dir][qp];
    const float4 b1 = g_bias4[dir][qp + 16];

    int buf = 0;
    for (; tile < PNT; tile += PGRIDX) {
        const int nxt = tile + PGRIDX;

        // async-stage next tile into the other buffer (flies under compute)
        if (nxt < PNT) {
            const float* sp = x + (size_t)nxt * (PROWS * II) + 2 * tid;
            u32 d = xsb + (u32)(buf ^ 1) * PSM_X + dof0;
            int kp = kp0;
            #pragma unroll
            for (int i = 0; i < 7; i++) {
                int n = tid + i * 256;
                if (n < NSTAGE) cpa8(d, sp);
                sp += 512;
                d += 266 * 8; kp += 6;
                if (kp >= PKP) { kp -= PKP; d += 8; }
            }
            CPA_COMMIT();
        }

        // ---- compute current tile ----
        u64 acc[4][8];
        #pragma unroll
        for (int r = 0; r < 4; r++)
            #pragma unroll
            for (int g = 0; g < 8; g++) acc[r][g] = 0ULL;

        const float2* xrow = (const float2*)(psm + PSM_W + buf * PSM_X) + rg * 4 * XPITCH;

        #pragma unroll 13
        for (int kpp = 0; kpp < 13; kpp++) {
            const int kpA = 2 * kpp, kpB = 2 * kpp + 1;   // kpB=25 pairs with zero w & zero x pad
            ulonglong2 wA01 = wqs[kpA][0][qp];
            ulonglong2 wA23 = wqs[kpA][1][qp];
            ulonglong2 wA45 = wqs[kpA][2][qp];
            ulonglong2 wA67 = wqs[kpA][3][qp];
            ulonglong2 wB01 = wqs[kpB][0][qp];
            ulonglong2 wB23 = wqs[kpB][1][qp];
            ulonglong2 wB45 = wqs[kpB][2][qp];
            ulonglong2 wB67 = wqs[kpB][3][qp];
            #pragma unroll
            for (int r = 0; r < 4; r++) {
                // one broadcast LDS.128 covers k-pairs kpA and kpB
                ulonglong2 xv = *(const ulonglong2*)&xrow[r * XPITCH + kpA];
                fma2(acc[r][0], wA01.x, xv.x); fma2(acc[r][1], wA01.y, xv.x);
                fma2(acc[r][2], wA23.x, xv.x); fma2(acc[r][3], wA23.y, xv.x);
                fma2(acc[r][4], wA45.x, xv.x); fma2(acc[r][5], wA45.y, xv.x);
                fma2(acc[r][6], wA67.x, xv.x); fma2(acc[r][7], wA67.y, xv.x);
                fma2(acc[r][0], wB01.x, xv.y); fma2(acc[r][1], wB01.y, xv.y);
                fma2(acc[r][2], wB23.x, xv.y); fma2(acc[r][3], wB23.y, xv.y);
                fma2(acc[r][4], wB45.x, xv.y); fma2(acc[r][5], wB45.y, xv.y);
                fma2(acc[r][6], wB67.x, xv.y); fma2(acc[r][7], wB67.y, xv.y);
            }
        }

        // ---- epilogue: reduce k-split pairs, add bias, quad STG ----
        const int m0 = tile * PROWS;
        #pragma unroll
        for (int r = 0; r < 4; r++) {
            int m = m0 + rg * 4 + r;
            int b = m >> 10;
            int t = m & (TT - 1);
            int tt = dir ? (TT - 1 - t) : t;
            float2 v0 = upk2(acc[r][0]), v1 = upk2(acc[r][1]);
            float2 v2 = upk2(acc[r][2]), v3 = upk2(acc[r][3]);
            float2 v4 = upk2(acc[r][4]), v5 = upk2(acc[r][5]);
            float2 v6 = upk2(acc[r][6]), v7 = upk2(acc[r][7]);
            float4 o0 = make_float4(v0.x + v0.y + b0.x, v1.x + v1.y + b0.y,
                                    v2.x + v2.y + b0.z, v3.x + v3.y + b0.w);
            float4 o1 = make_float4(v4.x + v4.y + b1.x, v5.x + v5.y + b1.y,
                                    v6.x + v6.y + b1.z, v7.x + v7.y + b1.w);
            g_xp4[dir][tt][b][qp]      = o0;
            g_xp4[dir][tt][b][qp + 16] = o1;
        }

        CPA_WAIT0();
        __syncthreads();
        buf ^= 1;
    }
}

// ---------------- ncu slot-shift dummies (land the capture slot on proj_kernel) ----------------
__global__ void dummy_kernel() {}
__global__ void dummy_kernel2() {}

// ---------------- recurrent scan: one WARP = one (dir, batch); barrier-free ----------------
// (round-8 exact: 370.8us measured; FROZEN — two alternatives both regressed)
__global__ void __launch_bounds__(128, 2) lstm_kernel() {
    const int tid = threadIdx.x;
    const int wrp = tid >> 5;
    const int j   = tid & 31;
    const int gw  = blockIdx.x * 4 + wrp;        // 0..1023
    const int dir = gw >> 9;
    const int b   = gw & 511;

    __shared__ __align__(16) float2 hbuf[4][2][HH];     // duplicated h pairs, double-buffered
    __shared__ float ystage[4][32][33];                 // staged y contributions (padded)

    u64 wif[HH], wgo[HH];
    #pragma unroll
    for (int k = 0; k < HH; k++) {
        wif[k] = *(const u64*)&g_whif2[dir][k][j];
        wgo[k] = *(const u64*)&g_whgo2[dir][k][j];
    }
    const float wej = g_weff[dir * HH + j];

    hbuf[wrp][0][j] = make_float2(0.f, 0.f);
    __syncwarp();

    const float4* __restrict__ xp = &g_xp4[dir][0][b][j];
    const int XS = BB * HH;

    // prefetch ring, depth 8
    float4 xr[8];
    #pragma unroll
    for (int p = 0; p < 8; p++) xr[p] = xp[p * XS];

    float c = 0.f;
    int pb = 0;

    #pragma unroll 8
    for (int t = 0; t < TT; t++) {
        float4 xc = xr[t & 7];
        u64 aif0 = pk2(xc.x, xc.y);
        u64 ago0 = pk2(xc.z, xc.w);
        u64 aif1 = pk2(0.f, 0.f);
        u64 ago1 = pk2(0.f, 0.f);

        const float2* hb = hbuf[wrp][pb];
        #pragma unroll
        for (int k2 = 0; k2 < HH / 2; k2++) {
            ulonglong2 hq = *(const ulonglong2*)&hb[2 * k2];   // uniform broadcast LDS.128
            fma2(aif0, wif[2 * k2],     hq.x);
            fma2(aif1, wif[2 * k2 + 1], hq.y);
            fma2(ago0, wgo[2 * k2],     hq.x);
            fma2(ago1, wgo[2 * k2 + 1], hq.y);
        }

        // prefetch t+8 (slot reuse)
        int tn = (t + 8 < TT) ? (t + 8) : (TT - 1);
        xr[t & 7] = xp[tn * XS];

        float2 zif = upk2(add2(aif0, aif1));
        float2 zgo = upk2(add2(ago0, ago1));
        float ig = sigm(zif.x), fg = sigm(zif.y);
        float gg = tanhx(zgo.x), og = sigm(zgo.y);
        c = fmaf(fg, c, ig * gg);
        float h = og * tanhx(c);

        hbuf[wrp][pb ^ 1][j] = make_float2(h, h);
        ystage[wrp][t & 31][j] = h * wej;        // staged FC contribution (no shfl chain)
        __syncwarp();

        if ((t & 31) == 31) {                    // transpose-reduce 32 outputs, off critical path
            float s = 0.f;
            #pragma unroll
            for (int k = 0; k < 32; k++) s += ystage[wrp][j][k];
            int tg = (t - 31) + j;
            int tout = dir ? (TT - 1 - tg) : tg;
            g_yp[dir][b * TT + tout] = s;
        }
        pb ^= 1;
    }
}

// ---------------- combine: out = yf + yr + b_eff ----------------
__global__ void combine_kernel(float* __restrict__ out) {
    int i = blockIdx.x * blockDim.x + threadIdx.x;
    if (i < BT) out[i] = g_yp[0][i] + g_yp[1][i] + g_beff;
}

extern "C" void kernel_launch(void* const* d_in, const int* in_sizes, int n_in,
                              void* d_out, int out_size) {
    const float* x     = (const float*)d_in[0];
    const float* wih_f = (const float*)d_in[1];
    const float* whh_f = (const float*)d_in[2];
    const float* bih_f = (const float*)d_in[3];
    const float* bhh_f = (const float*)d_in[4];
    const float* wih_r = (const float*)d_in[5];
    const float* whh_r = (const float*)d_in[6];
    const float* bih_r = (const float*)d_in[7];
    const float* bhh_r = (const float*)d_in[8];
    const float* fc1w  = (const float*)d_in[9];
    const float* fc1b  = (const float*)d_in[10];
    const float* fc3w  = (const float*)d_in[11];
    const float* fc3b  = (const float*)d_in[12];
    float* out = (float*)d_out;

    cudaFuncSetAttribute(proj_kernel, cudaFuncAttributeMaxDynamicSharedMemorySize, PSM_TOTAL);

    prep_kernel<<<32, 256>>>(wih_f, whh_f, bih_f, bhh_f,
                             wih_r, whh_r, bih_r, bhh_r,
                             fc1w, fc1b, fc3w, fc3b);

    dummy_kernel<<<1, 32>>>();   // slot shift: capture lands on our 4th launch
    dummy_kernel2<<<1, 32>>>();  // -> proj_kernel

    dim3 pg(PGRIDX, 2);
    proj_kernel<<<pg, 256, PSM_TOTAL>>>(x);

    lstm_kernel<<<256, 128>>>();

    combine_kernel<<<(BT + 255) / 256, 256>>>(out);
}